// round 5
// baseline (speedup 1.0000x reference)
#include <cuda_runtime.h>
#include <math.h>

#define NU 200000
#define NI 200000
#define D  128
#define B  4096
#define KRNN 264   // [x(129) | h(128) | pad(7)] ; 264 = 33*8

// ---- output layout (flattened tuple, row-major) ----
#define OFF_PRED       0
#define OFF_TARGET     (B*2*D)
#define OFF_UPD_USER   (OFF_TARGET + B*2*D)
#define OFF_USER_EMB   (OFF_UPD_USER + B*D)
#define OFF_UPD_ITEM   (OFF_USER_EMB + B*D)
#define OFF_ITEM_EMB   (OFF_UPD_ITEM + B*D)
#define OFF_DYN_USER   (OFF_ITEM_EMB + B*D)
#define OFF_DYN_ITEM   (OFF_DYN_USER + NU*D)
#define OFF_ISNEW_U    (OFF_DYN_ITEM + NI*D)
#define OFF_ISNEW_I    (OFF_ISNEW_U + NU)

// ---- device scratch ----
__device__ __align__(16) float g_Xpred[B * 512];
__device__ __align__(16) float g_Xu[B * KRNN];
__device__ __align__(16) float g_Xi[B * KRNN];
__device__ __align__(16) float g_Wu[D * KRNN];
__device__ __align__(16) float g_Wi[D * KRNN];
__device__ float g_bu[D];
__device__ float g_bi[D];
// winner sentinel: 0 = none, else b+1. Zero-init at load; scatter_kernel
// resets every entry it consumed, so each graph replay starts from all-zero.
__device__ int g_winner_u[NU];
__device__ int g_winner_i[NI];

typedef unsigned long long ull;
#define FFMA2(c, a, b) asm("fma.rn.f32x2 %0, %1, %2, %3;" \
    : "=l"(c) : "l"(a), "l"(b), "l"(c))
#define PACK2(d, x, y) asm("mov.b64 %0, {%1, %2};" : "=l"(d) : "f"(x), "f"(y))
#define UNPACK2(lo, hi, v) asm("mov.b64 {%0, %1}, %2;" : "=f"(lo), "=f"(hi) : "l"(v))

// ---------------------------------------------------------------------------
// last occurrence wins (CPU scatter order); sentinel b+1 over zero-init
__global__ void winner_kernel(const int* __restrict__ uid, const int* __restrict__ iid) {
    int b = blockIdx.x * blockDim.x + threadIdx.x;
    if (b < B) {
        atomicMax(&g_winner_u[uid[b]], b + 1);
        atomicMax(&g_winner_i[iid[b]], b + 1);
    }
}

// build combined RNN weights [Wih | Whh | 0] and fused biases
__global__ void prep_kernel(const float* __restrict__ uWih, const float* __restrict__ uWhh,
                            const float* __restrict__ ubih, const float* __restrict__ ubhh,
                            const float* __restrict__ iWih, const float* __restrict__ iWhh,
                            const float* __restrict__ ibih, const float* __restrict__ ibhh) {
    int i = blockIdx.x * blockDim.x + threadIdx.x;
    if (i < D * KRNN) {
        int n = i / KRNN, k = i % KRNN;
        float wu, wi;
        if (k < 129)      { wu = uWih[n * 129 + k];       wi = iWih[n * 129 + k]; }
        else if (k < 257) { wu = uWhh[n * 128 + (k-129)]; wi = iWhh[n * 128 + (k-129)]; }
        else              { wu = 0.f; wi = 0.f; }
        g_Wu[i] = wu; g_Wi[i] = wi;
    }
    if (i < D) { g_bu[i] = ubih[i] + ubhh[i]; g_bi[i] = ibih[i] + ibhh[i]; }
}

// ---------------------------------------------------------------------------
// bounded-grid bulk copy: dyn tables + is_new flags -> out, leaves SMs free
#define COPY_BLOCKS 64
#define COPY_THREADS 512
#define N4_U   (NU * D / 4)
#define N4_I   (NI * D / 4)
#define N4_ISU (NU / 4)
#define N4_ISI (NI / 4)
#define N4_TOT (N4_U + N4_I + N4_ISU + N4_ISI)

__global__ void __launch_bounds__(COPY_THREADS) copy_kernel(
        const float4* __restrict__ dynU, const float4* __restrict__ dynI,
        const float4* __restrict__ isU, const float4* __restrict__ isI,
        float4* __restrict__ out4dynU) {
    // dest region is contiguous: [DYN_USER | DYN_ITEM | ISNEW_U | ISNEW_I]
    int stride = COPY_BLOCKS * COPY_THREADS;
    for (int i = blockIdx.x * COPY_THREADS + threadIdx.x; i < N4_TOT; i += stride) {
        float4 v;
        if (i < N4_U)                     v = dynU[i];
        else if (i < N4_U + N4_I)         v = dynI[i - N4_U];
        else if (i < N4_U + N4_I + N4_ISU) v = isU[i - N4_U - N4_I];
        else                              v = isI[i - N4_U - N4_I - N4_ISU];
        out4dynU[i] = v;
    }
}

// ---------------------------------------------------------------------------
__global__ void gather_kernel(const int* __restrict__ uid, const int* __restrict__ pid,
                              const int* __restrict__ iid,
                              const float* __restrict__ t_item, const float* __restrict__ t_user,
                              const float* __restrict__ dynU, const float* __restrict__ dynI,
                              const float* __restrict__ isU, const float* __restrict__ isI,
                              const float* __restrict__ statU, const float* __restrict__ statI,
                              const float* __restrict__ initU, const float* __restrict__ initI,
                              const float* __restrict__ tdW, const float* __restrict__ tdb,
                              float* __restrict__ out) {
    int b = blockIdx.x;
    int d = threadIdx.x;           // 0..127
    int u = uid[b], p = pid[b], it = iid[b];
    float ti = t_item[b], tu = t_user[b];
    float fu = isU[u], fi = isI[it], fp = isI[p];

    float ue = fu * initU[d] + dynU[(long)u * D + d];
    float ie = fi * initI[d] + dynI[(long)it * D + d];
    float pe = fp * initI[d] + dynI[(long)p * D + d];
    float su = statU[(long)u * D + d];
    float si = statI[(long)it * D + d];
    float ps = statI[(long)p * D + d];

    out[OFF_USER_EMB + b * D + d] = ue;
    out[OFF_ITEM_EMB + b * D + d] = ie;
    out[OFF_TARGET + b * 2 * D + d]     = ie;
    out[OFF_TARGET + b * 2 * D + D + d] = si;

    float proj = ue * (1.f + ti * tdW[d] + tdb[d]);
    g_Xpred[b * 512 + d]       = proj;
    g_Xpred[b * 512 + 128 + d] = pe;
    g_Xpred[b * 512 + 256 + d] = ps;
    g_Xpred[b * 512 + 384 + d] = su;

    g_Xu[b * KRNN + d]       = ie;
    g_Xu[b * KRNN + 129 + d] = ue;
    g_Xi[b * KRNN + d]       = ue;
    g_Xi[b * KRNN + 129 + d] = ie;
    if (d == 0) {
        g_Xu[b * KRNN + 128] = ti;
        g_Xi[b * KRNN + 128] = tu;
    }
    if (d < KRNN - 257) {
        g_Xu[b * KRNN + 257 + d] = 0.f;
        g_Xi[b * KRNN + 257 + d] = 0.f;
    }
}

// ---------------------------------------------------------------------------
// C[m][n] = act( sum_k X[m][k]*W[n][k] + bias[n] )
// tile 64(M) x 64(N), BK=8, 128 threads, 8x4 microtile (M as 4 f32x2 pairs)
template <int KDIM, bool TANH>
__device__ __forceinline__ void gemm64_body(const float* __restrict__ X,
                                            const float* __restrict__ W,
                                            const float* __restrict__ bias,
                                            float* __restrict__ C, int ldc) {
    __shared__ __align__(16) float As[2][8][64];
    __shared__ __align__(16) float Bs[2][8][64];
    int tid = threadIdx.x;       // 0..127
    int m0 = blockIdx.x * 64;
    int n0 = blockIdx.y * 64;
    int tx = tid & 15;           // N dir (x4)
    int ty = tid >> 4;           // M dir (x8 = 4 f32x2 pairs)

    ull acc[4][4];
    #pragma unroll
    for (int i = 0; i < 4; i++)
        #pragma unroll
        for (int j = 0; j < 4; j++) acc[i][j] = 0ull;

    int lrow = tid >> 1;            // 0..63
    int lcol = (tid & 1) * 4;       // 0 or 4
    const float* srcA = X + (long)(m0 + lrow) * KDIM + lcol;
    const float* srcB = W + (long)(n0 + lrow) * KDIM + lcol;
    const int KT = KDIM / 8;

    float4 va = *(const float4*)srcA;
    float4 vb = *(const float4*)srcB;
    As[0][lcol + 0][lrow] = va.x; As[0][lcol + 1][lrow] = va.y;
    As[0][lcol + 2][lrow] = va.z; As[0][lcol + 3][lrow] = va.w;
    Bs[0][lcol + 0][lrow] = vb.x; Bs[0][lcol + 1][lrow] = vb.y;
    Bs[0][lcol + 2][lrow] = vb.z; Bs[0][lcol + 3][lrow] = vb.w;
    __syncthreads();

    int buf = 0;
    for (int kt = 0; kt < KT; kt++) {
        if (kt + 1 < KT) {
            va = *(const float4*)(srcA + (kt + 1) * 8);
            vb = *(const float4*)(srcB + (kt + 1) * 8);
        }
        #pragma unroll
        for (int k = 0; k < 8; k++) {
            ulonglong2 a01 = *(const ulonglong2*)&As[buf][k][ty * 8];
            ulonglong2 a23 = *(const ulonglong2*)&As[buf][k][ty * 8 + 4];
            float4 b0 = *(const float4*)&Bs[buf][k][tx * 4];
            ull bb[4];
            PACK2(bb[0], b0.x, b0.x); PACK2(bb[1], b0.y, b0.y);
            PACK2(bb[2], b0.z, b0.z); PACK2(bb[3], b0.w, b0.w);
            #pragma unroll
            for (int j = 0; j < 4; j++) {
                FFMA2(acc[0][j], a01.x, bb[j]);
                FFMA2(acc[1][j], a01.y, bb[j]);
                FFMA2(acc[2][j], a23.x, bb[j]);
                FFMA2(acc[3][j], a23.y, bb[j]);
            }
        }
        if (kt + 1 < KT) {
            buf ^= 1;
            As[buf][lcol + 0][lrow] = va.x; As[buf][lcol + 1][lrow] = va.y;
            As[buf][lcol + 2][lrow] = va.z; As[buf][lcol + 3][lrow] = va.w;
            Bs[buf][lcol + 0][lrow] = vb.x; Bs[buf][lcol + 1][lrow] = vb.y;
            Bs[buf][lcol + 2][lrow] = vb.z; Bs[buf][lcol + 3][lrow] = vb.w;
            __syncthreads();
        }
    }

    float4 bias4 = *(const float4*)&bias[n0 + tx * 4];
    float bn[4] = {bias4.x, bias4.y, bias4.z, bias4.w};
    #pragma unroll
    for (int p = 0; p < 4; p++) {
        int mlo = m0 + ty * 8 + 2 * p;
        float lo[4], hi[4];
        #pragma unroll
        for (int j = 0; j < 4; j++) {
            float l, h;
            UNPACK2(l, h, acc[p][j]);
            l += bn[j]; h += bn[j];
            if (TANH) { l = tanhf(l); h = tanhf(h); }
            lo[j] = l; hi[j] = h;
        }
        *(float4*)&C[(long)mlo * ldc + n0 + tx * 4]       = make_float4(lo[0], lo[1], lo[2], lo[3]);
        *(float4*)&C[(long)(mlo + 1) * ldc + n0 + tx * 4] = make_float4(hi[0], hi[1], hi[2], hi[3]);
    }
}

__global__ void __launch_bounds__(128) pred_gemm_kernel(const float* __restrict__ X,
                                                        const float* __restrict__ W,
                                                        const float* __restrict__ bias,
                                                        float* __restrict__ C) {
    gemm64_body<512, false>(X, W, bias, C, 256);
}

// both RNN cells in one launch: z=0 -> user, z=1 -> item
__global__ void __launch_bounds__(128) rnn_gemm_kernel(float* __restrict__ out) {
    if (blockIdx.z == 0)
        gemm64_body<KRNN, true>(g_Xu, g_Wu, g_bu, out + OFF_UPD_USER, 128);
    else
        gemm64_body<KRNN, true>(g_Xi, g_Wi, g_bi, out + OFF_UPD_ITEM, 128);
}

// ---------------------------------------------------------------------------
// patch winner rows, zero is_new for batch ids, reset consumed winner entries
__global__ void scatter_kernel(const int* __restrict__ uid, const int* __restrict__ iid,
                               float* __restrict__ out) {
    int gw = blockIdx.x * 8 + (threadIdx.x >> 5);
    int lane = threadIdx.x & 31;
    if (gw < B) {
        int id = uid[gw];
        if (lane == 0) out[OFF_ISNEW_U + id] = 0.f;
        if (g_winner_u[id] == gw + 1) {
            float4 v = *(const float4*)(out + OFF_UPD_USER + (long)gw * D + lane * 4);
            *(float4*)(out + OFF_DYN_USER + (long)id * D + lane * 4) = v;
            if (lane == 0) g_winner_u[id] = 0;   // restore zero state for next replay
        }
    } else {
        int b = gw - B;
        if (b < B) {
            int id = iid[b];
            if (lane == 0) out[OFF_ISNEW_I + id] = 0.f;
            if (g_winner_i[id] == b + 1) {
                float4 v = *(const float4*)(out + OFF_UPD_ITEM + (long)b * D + lane * 4);
                *(float4*)(out + OFF_DYN_ITEM + (long)id * D + lane * 4) = v;
                if (lane == 0) g_winner_i[id] = 0;
            }
        }
    }
}

// ---------------------------------------------------------------------------
extern "C" void kernel_launch(void* const* d_in, const int* in_sizes, int n_in,
                              void* d_out, int out_size) {
    const int*   uid   = (const int*)d_in[0];
    const int*   pid   = (const int*)d_in[1];
    const int*   iid   = (const int*)d_in[2];
    const float* tItem = (const float*)d_in[3];
    const float* tUser = (const float*)d_in[4];
    const float* dynU  = (const float*)d_in[5];
    const float* dynI  = (const float*)d_in[6];
    const float* isU   = (const float*)d_in[7];
    const float* isI   = (const float*)d_in[8];
    const float* statU = (const float*)d_in[9];
    const float* statI = (const float*)d_in[10];
    const float* initU = (const float*)d_in[11];
    const float* initI = (const float*)d_in[12];
    const float* uWih  = (const float*)d_in[13];
    const float* uWhh  = (const float*)d_in[14];
    const float* ubih  = (const float*)d_in[15];
    const float* ubhh  = (const float*)d_in[16];
    const float* iWih  = (const float*)d_in[17];
    const float* iWhh  = (const float*)d_in[18];
    const float* ibih  = (const float*)d_in[19];
    const float* ibhh  = (const float*)d_in[20];
    const float* predW = (const float*)d_in[21];
    const float* predb = (const float*)d_in[22];
    const float* tdW   = (const float*)d_in[23];
    const float* tdb   = (const float*)d_in[24];
    float* out = (float*)d_out;

    float *xpred;
    cudaGetSymbolAddress((void**)&xpred, g_Xpred);

    static cudaStream_t sCopy = nullptr, sRnn = nullptr;
    static cudaEvent_t evStart = nullptr, evG = nullptr, evCopy = nullptr, evRnn = nullptr;
    if (!sCopy) {
        int loPrio, hiPrio;
        cudaDeviceGetStreamPriorityRange(&loPrio, &hiPrio);
        cudaStreamCreateWithPriority(&sCopy, cudaStreamNonBlocking, loPrio);  // lowest
        cudaStreamCreateWithPriority(&sRnn, cudaStreamNonBlocking, hiPrio);
        cudaEventCreateWithFlags(&evStart, cudaEventDisableTiming);
        cudaEventCreateWithFlags(&evG, cudaEventDisableTiming);
        cudaEventCreateWithFlags(&evCopy, cudaEventDisableTiming);
        cudaEventCreateWithFlags(&evRnn, cudaEventDisableTiming);
    }

    cudaEventRecord(evStart, 0);

    // low-priority bounded copy: starts immediately, leaves SMs for compute
    cudaStreamWaitEvent(sCopy, evStart, 0);
    copy_kernel<<<COPY_BLOCKS, COPY_THREADS, 0, sCopy>>>(
        (const float4*)dynU, (const float4*)dynI,
        (const float4*)isU, (const float4*)isI,
        (float4*)(out + OFF_DYN_USER));
    cudaEventRecord(evCopy, sCopy);

    // rnn stream: winner + weight prep off the critical path
    cudaStreamWaitEvent(sRnn, evStart, 0);
    winner_kernel<<<(B + 255) / 256, 256, 0, sRnn>>>(uid, iid);
    prep_kernel<<<(D * KRNN + 255) / 256, 256, 0, sRnn>>>(uWih, uWhh, ubih, ubhh,
                                                          iWih, iWhh, ibih, ibhh);

    // main stream: gather -> pred GEMM
    gather_kernel<<<B, 128>>>(uid, pid, iid, tItem, tUser, dynU, dynI, isU, isI,
                              statU, statI, initU, initI, tdW, tdb, out);
    cudaEventRecord(evG, 0);

    cudaStreamWaitEvent(sRnn, evG, 0);
    rnn_gemm_kernel<<<dim3(64, 2, 2), 128, 0, sRnn>>>(out);
    cudaEventRecord(evRnn, sRnn);

    pred_gemm_kernel<<<dim3(64, 4), 128>>>(xpred, predW, predb, out + OFF_PRED);

    // join: patch winner rows once copy + RNN outputs exist
    cudaStreamWaitEvent(0, evCopy, 0);
    cudaStreamWaitEvent(0, evRnn, 0);
    scatter_kernel<<<(2 * B) / 8, 256>>>(uid, iid, out);
}

// round 6
// speedup vs baseline: 1.1103x; 1.1103x over previous
#include <cuda_runtime.h>
#include <math.h>

#define NU 200000
#define NI 200000
#define D  128
#define B  4096
#define KRNN 264   // [x(129) | h(128) | pad(7)] ; 264 = 33*8

// ---- output layout (flattened tuple, row-major) ----
#define OFF_PRED       0
#define OFF_TARGET     (B*2*D)
#define OFF_UPD_USER   (OFF_TARGET + B*2*D)
#define OFF_USER_EMB   (OFF_UPD_USER + B*D)
#define OFF_UPD_ITEM   (OFF_USER_EMB + B*D)
#define OFF_ITEM_EMB   (OFF_UPD_ITEM + B*D)
#define OFF_DYN_USER   (OFF_ITEM_EMB + B*D)
#define OFF_DYN_ITEM   (OFF_DYN_USER + NU*D)
#define OFF_ISNEW_U    (OFF_DYN_ITEM + NI*D)
#define OFF_ISNEW_I    (OFF_ISNEW_U + NU)

// ---- device scratch ----
__device__ __align__(16) float g_Xpred[B * 512];
__device__ __align__(16) float g_Xu[B * KRNN];
__device__ __align__(16) float g_Xi[B * KRNN];
__device__ __align__(16) float g_Wu[D * KRNN];
__device__ __align__(16) float g_Wi[D * KRNN];
__device__ float g_bu[D];
__device__ float g_bi[D];
// winner sentinel: 0 = none, else b+1. Zero-init at load; scatter_kernel
// resets every entry it consumed, so each graph replay starts from all-zero.
__device__ int g_winner_u[NU];
__device__ int g_winner_i[NI];

typedef unsigned long long ull;
#define FFMA2(c, a, b) asm("fma.rn.f32x2 %0, %1, %2, %3;" \
    : "=l"(c) : "l"(a), "l"(b), "l"(c))
#define PACK2(d, x, y) asm("mov.b64 %0, {%1, %2};" : "=l"(d) : "f"(x), "f"(y))
#define UNPACK2(lo, hi, v) asm("mov.b64 {%0, %1}, %2;" : "=f"(lo), "=f"(hi) : "l"(v))

// ---------------------------------------------------------------------------
// last occurrence wins (CPU scatter order); sentinel b+1 over zero-init
__global__ void winner_kernel(const int* __restrict__ uid, const int* __restrict__ iid) {
    int b = blockIdx.x * blockDim.x + threadIdx.x;
    if (b < B) {
        atomicMax(&g_winner_u[uid[b]], b + 1);
        atomicMax(&g_winner_i[iid[b]], b + 1);
    }
}

// build combined RNN weights [Wih | Whh | 0] and fused biases
__global__ void prep_kernel(const float* __restrict__ uWih, const float* __restrict__ uWhh,
                            const float* __restrict__ ubih, const float* __restrict__ ubhh,
                            const float* __restrict__ iWih, const float* __restrict__ iWhh,
                            const float* __restrict__ ibih, const float* __restrict__ ibhh) {
    int i = blockIdx.x * blockDim.x + threadIdx.x;
    if (i < D * KRNN) {
        int n = i / KRNN, k = i % KRNN;
        float wu, wi;
        if (k < 129)      { wu = uWih[n * 129 + k];       wi = iWih[n * 129 + k]; }
        else if (k < 257) { wu = uWhh[n * 128 + (k-129)]; wi = iWhh[n * 128 + (k-129)]; }
        else              { wu = 0.f; wi = 0.f; }
        g_Wu[i] = wu; g_Wi[i] = wi;
    }
    if (i < D) { g_bu[i] = ubih[i] + ubhh[i]; g_bi[i] = ibih[i] + ibhh[i]; }
}

// ---------------------------------------------------------------------------
// bounded-grid bulk copy with MLP=8: issue 8 independent LDG.128 before STGs
#define COPY_BLOCKS 128
#define COPY_THREADS 256
#define N4_U   (NU * D / 4)
#define N4_I   (NI * D / 4)
#define N4_ISU (NU / 4)
#define N4_ISI (NI / 4)

__device__ __forceinline__ void copy_seg(const float4* __restrict__ src,
                                         float4* __restrict__ dst, int n) {
    int stride = COPY_BLOCKS * COPY_THREADS;
    int i = blockIdx.x * COPY_THREADS + threadIdx.x;
    for (; i + 7 * stride < n; i += 8 * stride) {
        float4 v0 = src[i];
        float4 v1 = src[i + stride];
        float4 v2 = src[i + 2 * stride];
        float4 v3 = src[i + 3 * stride];
        float4 v4 = src[i + 4 * stride];
        float4 v5 = src[i + 5 * stride];
        float4 v6 = src[i + 6 * stride];
        float4 v7 = src[i + 7 * stride];
        dst[i]              = v0;
        dst[i + stride]     = v1;
        dst[i + 2 * stride] = v2;
        dst[i + 3 * stride] = v3;
        dst[i + 4 * stride] = v4;
        dst[i + 5 * stride] = v5;
        dst[i + 6 * stride] = v6;
        dst[i + 7 * stride] = v7;
    }
    for (; i < n; i += stride) dst[i] = src[i];
}

__global__ void __launch_bounds__(COPY_THREADS) copy_kernel(
        const float4* __restrict__ dynU, const float4* __restrict__ dynI,
        const float4* __restrict__ isU, const float4* __restrict__ isI,
        float* __restrict__ out) {
    copy_seg(dynU, (float4*)(out + OFF_DYN_USER), N4_U);
    copy_seg(dynI, (float4*)(out + OFF_DYN_ITEM), N4_I);
    copy_seg(isU,  (float4*)(out + OFF_ISNEW_U),  N4_ISU);
    copy_seg(isI,  (float4*)(out + OFF_ISNEW_I),  N4_ISI);
}

// ---------------------------------------------------------------------------
__global__ void gather_kernel(const int* __restrict__ uid, const int* __restrict__ pid,
                              const int* __restrict__ iid,
                              const float* __restrict__ t_item, const float* __restrict__ t_user,
                              const float* __restrict__ dynU, const float* __restrict__ dynI,
                              const float* __restrict__ isU, const float* __restrict__ isI,
                              const float* __restrict__ statU, const float* __restrict__ statI,
                              const float* __restrict__ initU, const float* __restrict__ initI,
                              const float* __restrict__ tdW, const float* __restrict__ tdb,
                              float* __restrict__ out) {
    int b = blockIdx.x;
    int d = threadIdx.x;           // 0..127
    int u = uid[b], p = pid[b], it = iid[b];
    float ti = t_item[b], tu = t_user[b];
    float fu = isU[u], fi = isI[it], fp = isI[p];

    float ue = fu * initU[d] + dynU[(long)u * D + d];
    float ie = fi * initI[d] + dynI[(long)it * D + d];
    float pe = fp * initI[d] + dynI[(long)p * D + d];
    float su = statU[(long)u * D + d];
    float si = statI[(long)it * D + d];
    float ps = statI[(long)p * D + d];

    out[OFF_USER_EMB + b * D + d] = ue;
    out[OFF_ITEM_EMB + b * D + d] = ie;
    out[OFF_TARGET + b * 2 * D + d]     = ie;
    out[OFF_TARGET + b * 2 * D + D + d] = si;

    float proj = ue * (1.f + ti * tdW[d] + tdb[d]);
    g_Xpred[b * 512 + d]       = proj;
    g_Xpred[b * 512 + 128 + d] = pe;
    g_Xpred[b * 512 + 256 + d] = ps;
    g_Xpred[b * 512 + 384 + d] = su;

    g_Xu[b * KRNN + d]       = ie;
    g_Xu[b * KRNN + 129 + d] = ue;
    g_Xi[b * KRNN + d]       = ue;
    g_Xi[b * KRNN + 129 + d] = ie;
    if (d == 0) {
        g_Xu[b * KRNN + 128] = ti;
        g_Xi[b * KRNN + 128] = tu;
    }
    if (d < KRNN - 257) {
        g_Xu[b * KRNN + 257 + d] = 0.f;
        g_Xi[b * KRNN + 257 + d] = 0.f;
    }
}

// ---------------------------------------------------------------------------
// C[m][n] = act( sum_k X[m][k]*W[n][k] + bias[n] )
// tile 64(M) x 64(N), BK=8, 128 threads, 8x4 microtile (M as 4 f32x2 pairs)
template <int KDIM, bool TANH>
__device__ __forceinline__ void gemm64_body(const float* __restrict__ X,
                                            const float* __restrict__ W,
                                            const float* __restrict__ bias,
                                            float* __restrict__ C, int ldc) {
    __shared__ __align__(16) float As[2][8][64];
    __shared__ __align__(16) float Bs[2][8][64];
    int tid = threadIdx.x;       // 0..127
    int m0 = blockIdx.x * 64;
    int n0 = blockIdx.y * 64;
    int tx = tid & 15;           // N dir (x4)
    int ty = tid >> 4;           // M dir (x8 = 4 f32x2 pairs)

    ull acc[4][4];
    #pragma unroll
    for (int i = 0; i < 4; i++)
        #pragma unroll
        for (int j = 0; j < 4; j++) acc[i][j] = 0ull;

    int lrow = tid >> 1;            // 0..63
    int lcol = (tid & 1) * 4;       // 0 or 4
    const float* srcA = X + (long)(m0 + lrow) * KDIM + lcol;
    const float* srcB = W + (long)(n0 + lrow) * KDIM + lcol;
    const int KT = KDIM / 8;

    float4 va = *(const float4*)srcA;
    float4 vb = *(const float4*)srcB;
    As[0][lcol + 0][lrow] = va.x; As[0][lcol + 1][lrow] = va.y;
    As[0][lcol + 2][lrow] = va.z; As[0][lcol + 3][lrow] = va.w;
    Bs[0][lcol + 0][lrow] = vb.x; Bs[0][lcol + 1][lrow] = vb.y;
    Bs[0][lcol + 2][lrow] = vb.z; Bs[0][lcol + 3][lrow] = vb.w;
    __syncthreads();

    int buf = 0;
    for (int kt = 0; kt < KT; kt++) {
        if (kt + 1 < KT) {
            va = *(const float4*)(srcA + (kt + 1) * 8);
            vb = *(const float4*)(srcB + (kt + 1) * 8);
        }
        #pragma unroll
        for (int k = 0; k < 8; k++) {
            ulonglong2 a01 = *(const ulonglong2*)&As[buf][k][ty * 8];
            ulonglong2 a23 = *(const ulonglong2*)&As[buf][k][ty * 8 + 4];
            float4 b0 = *(const float4*)&Bs[buf][k][tx * 4];
            ull bb[4];
            PACK2(bb[0], b0.x, b0.x); PACK2(bb[1], b0.y, b0.y);
            PACK2(bb[2], b0.z, b0.z); PACK2(bb[3], b0.w, b0.w);
            #pragma unroll
            for (int j = 0; j < 4; j++) {
                FFMA2(acc[0][j], a01.x, bb[j]);
                FFMA2(acc[1][j], a01.y, bb[j]);
                FFMA2(acc[2][j], a23.x, bb[j]);
                FFMA2(acc[3][j], a23.y, bb[j]);
            }
        }
        if (kt + 1 < KT) {
            buf ^= 1;
            As[buf][lcol + 0][lrow] = va.x; As[buf][lcol + 1][lrow] = va.y;
            As[buf][lcol + 2][lrow] = va.z; As[buf][lcol + 3][lrow] = va.w;
            Bs[buf][lcol + 0][lrow] = vb.x; Bs[buf][lcol + 1][lrow] = vb.y;
            Bs[buf][lcol + 2][lrow] = vb.z; Bs[buf][lcol + 3][lrow] = vb.w;
            __syncthreads();
        }
    }

    float4 bias4 = *(const float4*)&bias[n0 + tx * 4];
    float bn[4] = {bias4.x, bias4.y, bias4.z, bias4.w};
    #pragma unroll
    for (int p = 0; p < 4; p++) {
        int mlo = m0 + ty * 8 + 2 * p;
        float lo[4], hi[4];
        #pragma unroll
        for (int j = 0; j < 4; j++) {
            float l, h;
            UNPACK2(l, h, acc[p][j]);
            l += bn[j]; h += bn[j];
            if (TANH) { l = tanhf(l); h = tanhf(h); }
            lo[j] = l; hi[j] = h;
        }
        *(float4*)&C[(long)mlo * ldc + n0 + tx * 4]       = make_float4(lo[0], lo[1], lo[2], lo[3]);
        *(float4*)&C[(long)(mlo + 1) * ldc + n0 + tx * 4] = make_float4(hi[0], hi[1], hi[2], hi[3]);
    }
}

__global__ void __launch_bounds__(128) pred_gemm_kernel(const float* __restrict__ X,
                                                        const float* __restrict__ W,
                                                        const float* __restrict__ bias,
                                                        float* __restrict__ C) {
    gemm64_body<512, false>(X, W, bias, C, 256);
}

// both RNN cells in one launch: z=0 -> user, z=1 -> item
__global__ void __launch_bounds__(128) rnn_gemm_kernel(float* __restrict__ out) {
    if (blockIdx.z == 0)
        gemm64_body<KRNN, true>(g_Xu, g_Wu, g_bu, out + OFF_UPD_USER, 128);
    else
        gemm64_body<KRNN, true>(g_Xi, g_Wi, g_bi, out + OFF_UPD_ITEM, 128);
}

// ---------------------------------------------------------------------------
// patch winner rows, zero is_new for batch ids, reset consumed winner entries
__global__ void scatter_kernel(const int* __restrict__ uid, const int* __restrict__ iid,
                               float* __restrict__ out) {
    int gw = blockIdx.x * 8 + (threadIdx.x >> 5);
    int lane = threadIdx.x & 31;
    if (gw < B) {
        int id = uid[gw];
        if (lane == 0) out[OFF_ISNEW_U + id] = 0.f;
        if (g_winner_u[id] == gw + 1) {
            float4 v = *(const float4*)(out + OFF_UPD_USER + (long)gw * D + lane * 4);
            *(float4*)(out + OFF_DYN_USER + (long)id * D + lane * 4) = v;
            if (lane == 0) g_winner_u[id] = 0;   // restore zero state for next replay
        }
    } else {
        int b = gw - B;
        if (b < B) {
            int id = iid[b];
            if (lane == 0) out[OFF_ISNEW_I + id] = 0.f;
            if (g_winner_i[id] == b + 1) {
                float4 v = *(const float4*)(out + OFF_UPD_ITEM + (long)b * D + lane * 4);
                *(float4*)(out + OFF_DYN_ITEM + (long)id * D + lane * 4) = v;
                if (lane == 0) g_winner_i[id] = 0;
            }
        }
    }
}

// ---------------------------------------------------------------------------
extern "C" void kernel_launch(void* const* d_in, const int* in_sizes, int n_in,
                              void* d_out, int out_size) {
    const int*   uid   = (const int*)d_in[0];
    const int*   pid   = (const int*)d_in[1];
    const int*   iid   = (const int*)d_in[2];
    const float* tItem = (const float*)d_in[3];
    const float* tUser = (const float*)d_in[4];
    const float* dynU  = (const float*)d_in[5];
    const float* dynI  = (const float*)d_in[6];
    const float* isU   = (const float*)d_in[7];
    const float* isI   = (const float*)d_in[8];
    const float* statU = (const float*)d_in[9];
    const float* statI = (const float*)d_in[10];
    const float* initU = (const float*)d_in[11];
    const float* initI = (const float*)d_in[12];
    const float* uWih  = (const float*)d_in[13];
    const float* uWhh  = (const float*)d_in[14];
    const float* ubih  = (const float*)d_in[15];
    const float* ubhh  = (const float*)d_in[16];
    const float* iWih  = (const float*)d_in[17];
    const float* iWhh  = (const float*)d_in[18];
    const float* ibih  = (const float*)d_in[19];
    const float* ibhh  = (const float*)d_in[20];
    const float* predW = (const float*)d_in[21];
    const float* predb = (const float*)d_in[22];
    const float* tdW   = (const float*)d_in[23];
    const float* tdb   = (const float*)d_in[24];
    float* out = (float*)d_out;

    float *xpred;
    cudaGetSymbolAddress((void**)&xpred, g_Xpred);

    static cudaStream_t sCopy = nullptr, sRnn = nullptr;
    static cudaEvent_t evStart = nullptr, evG = nullptr, evCopy = nullptr, evRnn = nullptr;
    if (!sCopy) {
        int loPrio, hiPrio;
        cudaDeviceGetStreamPriorityRange(&loPrio, &hiPrio);
        cudaStreamCreateWithPriority(&sCopy, cudaStreamNonBlocking, loPrio);  // lowest
        cudaStreamCreateWithPriority(&sRnn, cudaStreamNonBlocking, hiPrio);
        cudaEventCreateWithFlags(&evStart, cudaEventDisableTiming);
        cudaEventCreateWithFlags(&evG, cudaEventDisableTiming);
        cudaEventCreateWithFlags(&evCopy, cudaEventDisableTiming);
        cudaEventCreateWithFlags(&evRnn, cudaEventDisableTiming);
    }

    cudaEventRecord(evStart, 0);

    // low-priority bounded copy (MLP=8): starts immediately, co-runs with compute
    cudaStreamWaitEvent(sCopy, evStart, 0);
    copy_kernel<<<COPY_BLOCKS, COPY_THREADS, 0, sCopy>>>(
        (const float4*)dynU, (const float4*)dynI,
        (const float4*)isU, (const float4*)isI, out);
    cudaEventRecord(evCopy, sCopy);

    // rnn stream: winner + weight prep off the critical path
    cudaStreamWaitEvent(sRnn, evStart, 0);
    winner_kernel<<<(B + 255) / 256, 256, 0, sRnn>>>(uid, iid);
    prep_kernel<<<(D * KRNN + 255) / 256, 256, 0, sRnn>>>(uWih, uWhh, ubih, ubhh,
                                                          iWih, iWhh, ibih, ibhh);

    // main stream: gather -> pred GEMM
    gather_kernel<<<B, 128>>>(uid, pid, iid, tItem, tUser, dynU, dynI, isU, isI,
                              statU, statI, initU, initI, tdW, tdb, out);
    cudaEventRecord(evG, 0);

    cudaStreamWaitEvent(sRnn, evG, 0);
    rnn_gemm_kernel<<<dim3(64, 2, 2), 128, 0, sRnn>>>(out);
    cudaEventRecord(evRnn, sRnn);

    pred_gemm_kernel<<<dim3(64, 4), 128>>>(xpred, predW, predb, out + OFF_PRED);

    // join: patch winner rows once copy + RNN outputs exist
    cudaStreamWaitEvent(0, evCopy, 0);
    cudaStreamWaitEvent(0, evRnn, 0);
    scatter_kernel<<<(2 * B) / 8, 256>>>(uid, iid, out);
}

// round 7
// speedup vs baseline: 2.1761x; 1.9599x over previous
#include <cuda_runtime.h>
#include <math.h>

#define NU 200000
#define NI 200000
#define D  128
#define B  4096
#define KRNN 264   // [x(129) | h(128) | pad(7)] ; 264 = 33*8

// ---- output layout (flattened tuple, row-major) ----
#define OFF_PRED       0
#define OFF_TARGET     (B*2*D)
#define OFF_UPD_USER   (OFF_TARGET + B*2*D)
#define OFF_USER_EMB   (OFF_UPD_USER + B*D)
#define OFF_UPD_ITEM   (OFF_USER_EMB + B*D)
#define OFF_ITEM_EMB   (OFF_UPD_ITEM + B*D)
#define OFF_DYN_USER   (OFF_ITEM_EMB + B*D)
#define OFF_DYN_ITEM   (OFF_DYN_USER + NU*D)
#define OFF_ISNEW_U    (OFF_DYN_ITEM + NI*D)
#define OFF_ISNEW_I    (OFF_ISNEW_U + NU)

// ---- device scratch ----
__device__ __align__(16) float g_Xpred[B * 512];
__device__ __align__(16) float g_Xu[B * KRNN];
__device__ __align__(16) float g_Xi[B * KRNN];
__device__ __align__(16) float g_Wu[D * KRNN];
__device__ __align__(16) float g_Wi[D * KRNN];
__device__ float g_bu[D];
__device__ float g_bi[D];
// winner sentinel: 0 = none, else b+1. Zero-init at load; scatter_kernel
// resets every entry it consumed, so each graph replay starts from all-zero.
__device__ int g_winner_u[NU];
__device__ int g_winner_i[NI];

typedef unsigned long long ull;
#define FFMA2(c, a, b) asm("fma.rn.f32x2 %0, %1, %2, %3;" \
    : "=l"(c) : "l"(a), "l"(b), "l"(c))
#define PACK2(d, x, y) asm("mov.b64 %0, {%1, %2};" : "=l"(d) : "f"(x), "f"(y))
#define UNPACK2(lo, hi, v) asm("mov.b64 {%0, %1}, %2;" : "=f"(lo), "=f"(hi) : "l"(v))

// ---- copy partitioning (in float4 units) ----
#define N4_U    (NU * D / 4)     // 6.4M
#define N4_I    (NI * D / 4)     // 6.4M
#define N4_ISU  (NU / 4)         // 50K
#define N4_ISI  (NI / 4)         // 50K
#define C1_DYNU 2000000          // dynU float4s copied in phase1

#define P1_COPY 256              // copy CTAs in phase1
#define P2_COPY 1280             // copy CTAs in phase2

// MLP=8 ranged copy: CTAs {cta in [0,ncta)} copy src[lo,hi) -> dst[lo,hi)
__device__ __forceinline__ void copy_range(const float4* __restrict__ src,
                                           float4* __restrict__ dst,
                                           int lo, int hi, int cta, int ncta) {
    int stride = ncta * 128;
    int i = lo + cta * 128 + (int)threadIdx.x;
    for (; i + 7 * stride < hi; i += 8 * stride) {
        float4 v0 = src[i];
        float4 v1 = src[i + stride];
        float4 v2 = src[i + 2 * stride];
        float4 v3 = src[i + 3 * stride];
        float4 v4 = src[i + 4 * stride];
        float4 v5 = src[i + 5 * stride];
        float4 v6 = src[i + 6 * stride];
        float4 v7 = src[i + 7 * stride];
        dst[i]              = v0;
        dst[i + stride]     = v1;
        dst[i + 2 * stride] = v2;
        dst[i + 3 * stride] = v3;
        dst[i + 4 * stride] = v4;
        dst[i + 5 * stride] = v5;
        dst[i + 6 * stride] = v6;
        dst[i + 7 * stride] = v7;
    }
    for (; i < hi; i += stride) dst[i] = src[i];
}

// ---------------------------------------------------------------------------
// phase1: [copy chunk1 | gather | winner | prep] fused in one launch
__global__ void __launch_bounds__(128) phase1_kernel(
        const int* __restrict__ uid, const int* __restrict__ pid,
        const int* __restrict__ iid,
        const float* __restrict__ t_item, const float* __restrict__ t_user,
        const float* __restrict__ dynU, const float* __restrict__ dynI,
        const float* __restrict__ isU, const float* __restrict__ isI,
        const float* __restrict__ statU, const float* __restrict__ statI,
        const float* __restrict__ initU, const float* __restrict__ initI,
        const float* __restrict__ tdW, const float* __restrict__ tdb,
        const float* __restrict__ uWih, const float* __restrict__ uWhh,
        const float* __restrict__ ubih, const float* __restrict__ ubhh,
        const float* __restrict__ iWih, const float* __restrict__ iWhh,
        const float* __restrict__ ibih, const float* __restrict__ ibhh,
        float* __restrict__ out) {
    int bx = blockIdx.x;

    if (bx < P1_COPY) {
        // is_new flags + first chunk of dynU
        copy_range((const float4*)isU, (float4*)(out + OFF_ISNEW_U),
                   0, N4_ISU, bx, P1_COPY);
        copy_range((const float4*)isI, (float4*)(out + OFF_ISNEW_I),
                   0, N4_ISI, bx, P1_COPY);
        copy_range((const float4*)dynU, (float4*)(out + OFF_DYN_USER),
                   0, C1_DYNU, bx, P1_COPY);
        return;
    }
    bx -= P1_COPY;

    if (bx < B) {
        // ---- gather: one block per batch row ----
        int b = bx;
        int d = threadIdx.x;           // 0..127
        int u = uid[b], p = pid[b], it = iid[b];
        float ti = t_item[b], tu = t_user[b];
        float fu = isU[u], fi = isI[it], fp = isI[p];

        float ue = fu * initU[d] + dynU[(long)u * D + d];
        float ie = fi * initI[d] + dynI[(long)it * D + d];
        float pe = fp * initI[d] + dynI[(long)p * D + d];
        float su = statU[(long)u * D + d];
        float si = statI[(long)it * D + d];
        float ps = statI[(long)p * D + d];

        out[OFF_USER_EMB + b * D + d] = ue;
        out[OFF_ITEM_EMB + b * D + d] = ie;
        out[OFF_TARGET + b * 2 * D + d]     = ie;
        out[OFF_TARGET + b * 2 * D + D + d] = si;

        float proj = ue * (1.f + ti * tdW[d] + tdb[d]);
        g_Xpred[b * 512 + d]       = proj;
        g_Xpred[b * 512 + 128 + d] = pe;
        g_Xpred[b * 512 + 256 + d] = ps;
        g_Xpred[b * 512 + 384 + d] = su;

        g_Xu[b * KRNN + d]       = ie;
        g_Xu[b * KRNN + 129 + d] = ue;
        g_Xi[b * KRNN + d]       = ue;
        g_Xi[b * KRNN + 129 + d] = ie;
        if (d == 0) {
            g_Xu[b * KRNN + 128] = ti;
            g_Xi[b * KRNN + 128] = tu;
        }
        if (d < KRNN - 257) {
            g_Xu[b * KRNN + 257 + d] = 0.f;
            g_Xi[b * KRNN + 257 + d] = 0.f;
        }
        return;
    }
    bx -= B;

    if (bx < B / 128) {
        // ---- winner: last occurrence wins; sentinel b+1 over zero-init ----
        int b = bx * 128 + threadIdx.x;
        atomicMax(&g_winner_u[uid[b]], b + 1);
        atomicMax(&g_winner_i[iid[b]], b + 1);
        return;
    }
    bx -= B / 128;

    {
        // ---- prep: combined RNN weights [Wih | Whh | 0] + fused biases ----
        int i = bx * 128 + threadIdx.x;
        if (i < D * KRNN) {
            int n = i / KRNN, k = i % KRNN;
            float wu, wi;
            if (k < 129)      { wu = uWih[n * 129 + k];       wi = iWih[n * 129 + k]; }
            else if (k < 257) { wu = uWhh[n * 128 + (k-129)]; wi = iWhh[n * 128 + (k-129)]; }
            else              { wu = 0.f; wi = 0.f; }
            g_Wu[i] = wu; g_Wi[i] = wi;
        }
        if (i < D) { g_bu[i] = ubih[i] + ubhh[i]; g_bi[i] = ibih[i] + ibhh[i]; }
    }
}
#define P1_GRID (P1_COPY + B + B/128 + (D*KRNN + 127)/128)

// ---------------------------------------------------------------------------
// C[m][n] = act( sum_k X[m][k]*W[n][k] + bias[n] )
// tile 64(M) x 64(N), BK=8, 128 threads, 8x4 microtile (M as 4 f32x2 pairs)
template <int KDIM, bool TANH>
__device__ __forceinline__ void gemm64_body(int m0, int n0,
                                            const float* __restrict__ X,
                                            const float* __restrict__ W,
                                            const float* __restrict__ bias,
                                            float* __restrict__ C, int ldc) {
    __shared__ __align__(16) float As[2][8][64];
    __shared__ __align__(16) float Bs[2][8][64];
    int tid = threadIdx.x;       // 0..127
    int tx = tid & 15;           // N dir (x4)
    int ty = tid >> 4;           // M dir (x8 = 4 f32x2 pairs)

    ull acc[4][4];
    #pragma unroll
    for (int i = 0; i < 4; i++)
        #pragma unroll
        for (int j = 0; j < 4; j++) acc[i][j] = 0ull;

    int lrow = tid >> 1;            // 0..63
    int lcol = (tid & 1) * 4;       // 0 or 4
    const float* srcA = X + (long)(m0 + lrow) * KDIM + lcol;
    const float* srcB = W + (long)(n0 + lrow) * KDIM + lcol;
    const int KT = KDIM / 8;

    float4 va = *(const float4*)srcA;
    float4 vb = *(const float4*)srcB;
    As[0][lcol + 0][lrow] = va.x; As[0][lcol + 1][lrow] = va.y;
    As[0][lcol + 2][lrow] = va.z; As[0][lcol + 3][lrow] = va.w;
    Bs[0][lcol + 0][lrow] = vb.x; Bs[0][lcol + 1][lrow] = vb.y;
    Bs[0][lcol + 2][lrow] = vb.z; Bs[0][lcol + 3][lrow] = vb.w;
    __syncthreads();

    int buf = 0;
    for (int kt = 0; kt < KT; kt++) {
        if (kt + 1 < KT) {
            va = *(const float4*)(srcA + (kt + 1) * 8);
            vb = *(const float4*)(srcB + (kt + 1) * 8);
        }
        #pragma unroll
        for (int k = 0; k < 8; k++) {
            ulonglong2 a01 = *(const ulonglong2*)&As[buf][k][ty * 8];
            ulonglong2 a23 = *(const ulonglong2*)&As[buf][k][ty * 8 + 4];
            float4 b0 = *(const float4*)&Bs[buf][k][tx * 4];
            ull bb[4];
            PACK2(bb[0], b0.x, b0.x); PACK2(bb[1], b0.y, b0.y);
            PACK2(bb[2], b0.z, b0.z); PACK2(bb[3], b0.w, b0.w);
            #pragma unroll
            for (int j = 0; j < 4; j++) {
                FFMA2(acc[0][j], a01.x, bb[j]);
                FFMA2(acc[1][j], a01.y, bb[j]);
                FFMA2(acc[2][j], a23.x, bb[j]);
                FFMA2(acc[3][j], a23.y, bb[j]);
            }
        }
        if (kt + 1 < KT) {
            buf ^= 1;
            As[buf][lcol + 0][lrow] = va.x; As[buf][lcol + 1][lrow] = va.y;
            As[buf][lcol + 2][lrow] = va.z; As[buf][lcol + 3][lrow] = va.w;
            Bs[buf][lcol + 0][lrow] = vb.x; Bs[buf][lcol + 1][lrow] = vb.y;
            Bs[buf][lcol + 2][lrow] = vb.z; Bs[buf][lcol + 3][lrow] = vb.w;
            __syncthreads();
        }
    }

    float4 bias4 = *(const float4*)&bias[n0 + tx * 4];
    float bn[4] = {bias4.x, bias4.y, bias4.z, bias4.w};
    #pragma unroll
    for (int p = 0; p < 4; p++) {
        int mlo = m0 + ty * 8 + 2 * p;
        float lo[4], hi[4];
        #pragma unroll
        for (int j = 0; j < 4; j++) {
            float l, h;
            UNPACK2(l, h, acc[p][j]);
            l += bn[j]; h += bn[j];
            if (TANH) { l = tanhf(l); h = tanhf(h); }
            lo[j] = l; hi[j] = h;
        }
        *(float4*)&C[(long)mlo * ldc + n0 + tx * 4]       = make_float4(lo[0], lo[1], lo[2], lo[3]);
        *(float4*)&C[(long)(mlo + 1) * ldc + n0 + tx * 4] = make_float4(hi[0], hi[1], hi[2], hi[3]);
    }
}

// ---------------------------------------------------------------------------
// phase2: [pred GEMM | RNN GEMMs | copy chunk2] fused in one launch
__global__ void __launch_bounds__(128) phase2_kernel(
        const float* __restrict__ dynU, const float* __restrict__ dynI,
        const float* __restrict__ predW, const float* __restrict__ predb,
        float* __restrict__ out) {
    int bx = blockIdx.x;

    if (bx < 256) {
        // pred: 64 M-tiles x 4 N-tiles
        int m0 = (bx & 63) * 64;
        int n0 = (bx >> 6) * 64;
        gemm64_body<512, false>(m0, n0, g_Xpred, predW, predb, out + OFF_PRED, 256);
        return;
    }
    bx -= 256;

    if (bx < 256) {
        // RNN cells: 64 M-tiles x 2 N-tiles x 2 cells
        int cell = bx >> 7;
        int r = bx & 127;
        int m0 = (r & 63) * 64;
        int n0 = (r >> 6) * 64;
        if (cell == 0)
            gemm64_body<KRNN, true>(m0, n0, g_Xu, g_Wu, g_bu, out + OFF_UPD_USER, 128);
        else
            gemm64_body<KRNN, true>(m0, n0, g_Xi, g_Wi, g_bi, out + OFF_UPD_ITEM, 128);
        return;
    }
    bx -= 256;

    // copy chunk2: rest of dynU + all of dynI
    copy_range((const float4*)dynU, (float4*)(out + OFF_DYN_USER),
               C1_DYNU, N4_U, bx, P2_COPY);
    copy_range((const float4*)dynI, (float4*)(out + OFF_DYN_ITEM),
               0, N4_I, bx, P2_COPY);
}
#define P2_GRID (256 + 256 + P2_COPY)

// ---------------------------------------------------------------------------
// patch winner rows, zero is_new for batch ids, reset consumed winner entries
__global__ void scatter_kernel(const int* __restrict__ uid, const int* __restrict__ iid,
                               float* __restrict__ out) {
    int gw = blockIdx.x * 8 + (threadIdx.x >> 5);
    int lane = threadIdx.x & 31;
    if (gw < B) {
        int id = uid[gw];
        if (lane == 0) out[OFF_ISNEW_U + id] = 0.f;
        if (g_winner_u[id] == gw + 1) {
            float4 v = *(const float4*)(out + OFF_UPD_USER + (long)gw * D + lane * 4);
            *(float4*)(out + OFF_DYN_USER + (long)id * D + lane * 4) = v;
            if (lane == 0) g_winner_u[id] = 0;   // restore zero state for next replay
        }
    } else {
        int b = gw - B;
        if (b < B) {
            int id = iid[b];
            if (lane == 0) out[OFF_ISNEW_I + id] = 0.f;
            if (g_winner_i[id] == b + 1) {
                float4 v = *(const float4*)(out + OFF_UPD_ITEM + (long)b * D + lane * 4);
                *(float4*)(out + OFF_DYN_ITEM + (long)id * D + lane * 4) = v;
                if (lane == 0) g_winner_i[id] = 0;
            }
        }
    }
}

// ---------------------------------------------------------------------------
extern "C" void kernel_launch(void* const* d_in, const int* in_sizes, int n_in,
                              void* d_out, int out_size) {
    const int*   uid   = (const int*)d_in[0];
    const int*   pid   = (const int*)d_in[1];
    const int*   iid   = (const int*)d_in[2];
    const float* tItem = (const float*)d_in[3];
    const float* tUser = (const float*)d_in[4];
    const float* dynU  = (const float*)d_in[5];
    const float* dynI  = (const float*)d_in[6];
    const float* isU   = (const float*)d_in[7];
    const float* isI   = (const float*)d_in[8];
    const float* statU = (const float*)d_in[9];
    const float* statI = (const float*)d_in[10];
    const float* initU = (const float*)d_in[11];
    const float* initI = (const float*)d_in[12];
    const float* uWih  = (const float*)d_in[13];
    const float* uWhh  = (const float*)d_in[14];
    const float* ubih  = (const float*)d_in[15];
    const float* ubhh  = (const float*)d_in[16];
    const float* iWih  = (const float*)d_in[17];
    const float* iWhh  = (const float*)d_in[18];
    const float* ibih  = (const float*)d_in[19];
    const float* ibhh  = (const float*)d_in[20];
    const float* predW = (const float*)d_in[21];
    const float* predb = (const float*)d_in[22];
    const float* tdW   = (const float*)d_in[23];
    const float* tdb   = (const float*)d_in[24];
    float* out = (float*)d_out;

    phase1_kernel<<<P1_GRID, 128>>>(uid, pid, iid, tItem, tUser, dynU, dynI,
                                    isU, isI, statU, statI, initU, initI,
                                    tdW, tdb, uWih, uWhh, ubih, ubhh,
                                    iWih, iWhh, ibih, ibhh, out);
    phase2_kernel<<<P2_GRID, 128>>>(dynU, dynI, predW, predb, out);
    scatter_kernel<<<(2 * B) / 8, 256>>>(uid, iid, out);
}